// round 13
// baseline (speedup 1.0000x reference)
#include <cuda_runtime.h>
#include <cuda_fp16.h>
#include <stdint.h>

// ============================================================================
// Llama4TextExperts grouped GEMM + SwiGLU, fp32 in/out. Single-term fp16 HMMA.
//  GEMM1: CTA 128x256, 8 consumer warps @64x64 (2m x 4n) + 2 producer warps,
//         320 threads, 3-stage 48KB ring. SwiGLU -> g_scr fp16.
//  GEMM2: R11-proven: CTA 128x128, 8 consumers @32x64 + 4 producers, 384 thr.
// ============================================================================

#define NSM 148
#define ST1 49152
#define SMEM1 (1024 + 3 * ST1)
#define ST2 32768
#define SMEM2 (1024 + 4 * ST2)

static __device__ __half g_scr[(size_t)8 * 1024 * 4096];   // 64 MB fp16 inter

// ---------------- helpers ----------------
__device__ __forceinline__ uint32_t s2u(const void* p) {
    uint32_t a;
    asm("{ .reg .u64 t; cvta.to.shared.u64 t, %1; cvt.u32.u64 %0, t; }" : "=r"(a) : "l"(p));
    return a;
}
__device__ __forceinline__ uint32_t swzA(uint32_t o) { return o ^ ((o >> 3) & 0x70); }  // 128B rows
__device__ __forceinline__ uint32_t swzB(uint32_t o) { return o ^ ((o >> 4) & 0x70); }  // 256B rows
__device__ __forceinline__ uint32_t swzC(uint32_t o) { return o ^ ((o >> 5) & 0x70); }  // 512B rows

__device__ __forceinline__ uint32_t pkh(float a, float b) {
    __half2 h = __floats2half2_rn(a, b);
    return *reinterpret_cast<uint32_t*>(&h);
}
__device__ __forceinline__ float silu_mul(float g, float u) {
    return u * __fdividef(g, 1.0f + __expf(-g));
}
__device__ __forceinline__ void ldsm4(uint32_t* r, uint32_t addr) {
    asm volatile("ldmatrix.sync.aligned.m8n8.x4.shared.b16 {%0,%1,%2,%3}, [%4];"
                 : "=r"(r[0]), "=r"(r[1]), "=r"(r[2]), "=r"(r[3]) : "r"(addr));
}
__device__ __forceinline__ void ldsm4t(uint32_t* r, uint32_t addr) {
    asm volatile("ldmatrix.sync.aligned.m8n8.x4.trans.shared.b16 {%0,%1,%2,%3}, [%4];"
                 : "=r"(r[0]), "=r"(r[1]), "=r"(r[2]), "=r"(r[3]) : "r"(addr));
}
__device__ __forceinline__ void mma16816(float* c, const uint32_t* a, const uint32_t* b) {
    asm volatile(
        "mma.sync.aligned.m16n8k16.row.col.f32.f16.f16.f32 "
        "{%0,%1,%2,%3}, {%4,%5,%6,%7}, {%8,%9}, {%0,%1,%2,%3};"
        : "+f"(c[0]), "+f"(c[1]), "+f"(c[2]), "+f"(c[3])
        : "r"(a[0]), "r"(a[1]), "r"(a[2]), "r"(a[3]), "r"(b[0]), "r"(b[1]));
}

#define MBAR_INIT(addr, cnt) \
    asm volatile("mbarrier.init.shared.b64 [%0], %1;" :: "r"(addr), "r"((uint32_t)(cnt)) : "memory")
#define MBAR_ARRIVE(addr) \
    asm volatile("mbarrier.arrive.shared.b64 _, [%0];" :: "r"(addr) : "memory")
#define MBAR_WAIT(mbar_addr, phase_parity) do {                                            \
    uint32_t _mbar = (uint32_t)(mbar_addr);                                                \
    uint32_t _par  = (uint32_t)(phase_parity);                                             \
    uint32_t _done;                                                                        \
    asm volatile(                                                                          \
        "{\n\t.reg .pred p;\n\t"                                                           \
        "mbarrier.try_wait.parity.acquire.cta.shared::cta.b64 p, [%1], %2;\n\t"            \
        "selp.b32 %0, 1, 0, p;\n\t}"                                                       \
        : "=r"(_done) : "r"(_mbar), "r"(_par) : "memory");                                 \
    if (!_done) {                                                                          \
        asm volatile(                                                                      \
            "{\n\t.reg .pred P1;\n\t"                                                      \
            "WL_%=:\n\t"                                                                   \
            "mbarrier.try_wait.parity.acquire.cta.shared::cta.b64 P1, [%0], %1, 0x989680;\n\t" \
            "@P1 bra.uni WD_%=;\n\t"                                                       \
            "bra.uni WL_%=;\n\t"                                                           \
            "WD_%=:\n\t}"                                                                  \
            :: "r"(_mbar), "r"(_par) : "memory");                                          \
    }                                                                                      \
} while (0)

// ============================================================================
// GEMM1: X(8,1024,2048) @ Wgu(8,2048,8192) -> SwiGLU -> g_scr fp16.
// CTA tile 128m x 256n (128 gate + 128 up pairs, warp-paired at 32 cols).
// Stage (48KB): A@0 (128r x 128B, swzA), B@16K (64 k-rows x 512B, swzC).
// 320 thr = 8 consumers (2m x 4n, 64x64) + 2 producers.
// ============================================================================
__global__ __launch_bounds__(320, 1) void gemm1_ker(const float* __restrict__ A_,
                                                    const float* __restrict__ B_) {
    extern __shared__ char smem[];
    constexpr int NC = 32;          // 2048 / 64
    constexpr int PERE = 256;       // 8 mt * 32 nt
    constexpr int TOT = 2048;

    const int tid = threadIdx.x, wid = tid >> 5, lane = tid & 31;
    const uint32_t smbase = s2u(smem), tiles_u = (smbase + 1023) & ~1023u;
    char* tiles = smem + (tiles_u - smbase);
    const uint32_t full0 = smbase, empty0 = smbase + 24;
    if (tid == 0) {
        #pragma unroll
        for (int s = 0; s < 3; s++) { MBAR_INIT(full0 + 8 * s, 64); MBAR_INIT(empty0 + 8 * s, 8); }
    }
    __syncthreads();

    if (tid >= 256) {
        // ------------------------- producers (2 warps) -------------------------
        const int pt = tid - 256;            // 0..63
        const int a_c4 = pt & 15;            // float4 unit in 64-k row
        const int a_r0 = pt >> 4;            // 0..3
        const int half = pt >> 5;            // 0=gate, 1=up
        const int plane = pt & 31;
        // tile-local col for this thread's 4 pairs
        const int npr = (plane >> 3) * 64 + half * 32 + (plane & 7) * 4;

        int s = 0, u = 0;
        for (int t = blockIdx.x; t < TOT; t += gridDim.x) {
            const int e = t >> 8, r = t & 255, sup = r >> 6, r2 = r & 63;
            const int mt = r2 & 7, nt = sup * 8 + (r2 >> 3);
            const float* Apf = A_ + (size_t)(e * 1024 + mt * 128) * 2048 + a_c4 * 4;
            const float* Bp  = B_ + (size_t)e * 2048 * 8192
                             + (size_t)nt * 128 + plane * 4 + (size_t)half * 4096;
            for (int c = 0; c < NC; c++) {
                MBAR_WAIT(empty0 + 8 * s, u ^ 1);
                char* stg = tiles + s * ST1;
                const int kb = c * 64;
                // A: 128 rows x 64 k fp32 -> fp16 (32 loads/thread)
                #pragma unroll 8
                for (int p = 0; p < 32; p++) {
                    const int row = a_r0 + p * 4;
                    float4 v = *reinterpret_cast<const float4*>(Apf + (size_t)row * 2048 + kb);
                    const uint32_t off = swzA((uint32_t)(row * 128 + a_c4 * 8));
                    *reinterpret_cast<uint2*>(stg + off) = make_uint2(pkh(v.x, v.y), pkh(v.z, v.w));
                }
                // B: 64 k-rows x 256 tile cols (contiguous LDG, paired STS)
                #pragma unroll 8
                for (int k = 0; k < 64; k++) {
                    float4 v = *reinterpret_cast<const float4*>(Bp + (size_t)(kb + k) * 8192);
                    const uint32_t off = swzC((uint32_t)(k * 512 + npr * 2));
                    *reinterpret_cast<uint2*>(stg + 16384 + off) =
                        make_uint2(pkh(v.x, v.y), pkh(v.z, v.w));
                }
                MBAR_ARRIVE(full0 + 8 * s);
                if (++s == 3) { s = 0; u ^= 1; }
            }
        }
        return;
    }

    // ------------------------- consumers: 2m x 4n, 64x64 -------------------------
    const int wm = wid >> 2, wn = wid & 3;
    const int lane15 = lane & 15, seg = (lane >> 4) * 16;
    const uint32_t lxor = (uint32_t)((lane & 7) << 4);
    uint32_t a_row[4], b_colx[4];
    #pragma unroll
    for (int st = 0; st < 4; st++)
        a_row[st] = (uint32_t)((wm * 64 + st * 16 + lane15) * 128);
    #pragma unroll
    for (int ng = 0; ng < 4; ng++)
        b_colx[ng] = (uint32_t)(((wn * 64 + ng * 16) * 2 + seg)) ^ lxor;
    const uint32_t b_rowb = (uint32_t)(lane15 * 512);

    int s = 0, u = 0;
    for (int t = blockIdx.x; t < TOT; t += gridDim.x) {
        const int e = t >> 8, r = t & 255, sup = r >> 6, r2 = r & 63;
        const int mt = r2 & 7, nt = sup * 8 + (r2 >> 3);

        float acc[4][8][4];
        #pragma unroll
        for (int st = 0; st < 4; st++)
            #pragma unroll
            for (int j = 0; j < 8; j++)
                #pragma unroll
                for (int i = 0; i < 4; i++) acc[st][j][i] = 0.0f;

        for (int c = 0; c < NC; c++) {
            MBAR_WAIT(full0 + 8 * s, u);
            const uint32_t AhU = tiles_u + s * ST1;
            const uint32_t BhU = AhU + 16384;
            #pragma unroll
            for (int ks = 0; ks < 4; ks++) {
                const uint32_t acol = (uint32_t)(ks * 32 + seg) ^ lxor;
                const uint32_t brow = b_rowb + (uint32_t)(ks * 8192);
                uint32_t ah[4][4], bh[4][4];
                #pragma unroll
                for (int st = 0; st < 4; st++)
                    ldsm4(ah[st], AhU + a_row[st] + acol);
                #pragma unroll
                for (int ng = 0; ng < 4; ng++)
                    ldsm4t(bh[ng], BhU + brow + b_colx[ng]);
                #pragma unroll
                for (int st = 0; st < 4; st++)
                    #pragma unroll
                    for (int ng = 0; ng < 4; ng++)
                        #pragma unroll
                        for (int hf = 0; hf < 2; hf++)
                            mma16816(acc[st][ng * 2 + hf], ah[st], &bh[ng][2 * hf]);
            }
            if (lane == 0) MBAR_ARRIVE(empty0 + 8 * s);
            if (++s == 3) { s = 0; u ^= 1; }
        }

        // epilogue: register SwiGLU -> g_scr (gate = j<4, up = j+4)
        __half* scrb = g_scr + (size_t)(e * 1024 + mt * 128) * 4096
                     + (size_t)nt * 128 + wn * 32;
        #pragma unroll
        for (int st = 0; st < 4; st++)
            #pragma unroll
            for (int j = 0; j < 4; j++) {
                const int r0 = wm * 64 + st * 16 + (lane >> 2);
                const int cc = j * 8 + (lane & 3) * 2;
                const float i0 = silu_mul(acc[st][j][0], acc[st][j + 4][0]);
                const float i1 = silu_mul(acc[st][j][1], acc[st][j + 4][1]);
                const float i2 = silu_mul(acc[st][j][2], acc[st][j + 4][2]);
                const float i3 = silu_mul(acc[st][j][3], acc[st][j + 4][3]);
                *reinterpret_cast<uint32_t*>(scrb + (size_t)r0 * 4096 + cc) = pkh(i0, i1);
                *reinterpret_cast<uint32_t*>(scrb + (size_t)(r0 + 8) * 4096 + cc) = pkh(i2, i3);
            }
    }
}

// ============================================================================
// GEMM2 (R11-proven): g_scr @ Wd -> out. CTA 128x128, 8 consumers @32x64.
// ============================================================================
__global__ __launch_bounds__(384, 1) void gemm2_ker(const float* __restrict__ B_,
                                                    float* __restrict__ C_) {
    extern __shared__ char smem[];
    constexpr int NC = 64, PERE = 128, TOT = 1024;
    const int tid = threadIdx.x, wid = tid >> 5, lane = tid & 31;
    const uint32_t smbase = s2u(smem), tiles_u = (smbase + 1023) & ~1023u;
    char* tiles = smem + (tiles_u - smbase);
    const uint32_t full0 = smbase, empty0 = smbase + 32;
    if (tid == 0) {
        #pragma unroll
        for (int s = 0; s < 4; s++) { MBAR_INIT(full0 + 8 * s, 128); MBAR_INIT(empty0 + 8 * s, 8); }
    }
    __syncthreads();

    if (tid >= 256) {
        const int pt = tid - 256;
        const int a_c4 = pt & 15, a_r0 = pt >> 4;
        const int b_n4 = pt & 31, b_k0 = pt >> 5;
        int s = 0, u = 0;
        for (int t = blockIdx.x; t < TOT; t += gridDim.x) {
            const int e = t >> 7, r = t & 127, sup = r >> 6, r2 = r & 63;
            const int mt = r2 & 7, nt = sup * 8 + (r2 >> 3);
            const __half* Aph = g_scr + (size_t)(e * 1024 + mt * 128) * 4096 + a_c4 * 4;
            const float* Bp = B_ + (size_t)e * 4096 * 2048 + (size_t)nt * 128 + b_n4 * 4;
            for (int c = 0; c < NC; c++) {
                MBAR_WAIT(empty0 + 8 * s, u ^ 1);
                char* stg = tiles + s * ST2;
                const int kb = c * 64;
                #pragma unroll
                for (int p = 0; p < 16; p++) {
                    const int row = a_r0 + p * 8;
                    const uint32_t off = swzA((uint32_t)(row * 128 + a_c4 * 8));
                    *reinterpret_cast<uint2*>(stg + off) =
                        *reinterpret_cast<const uint2*>(Aph + (size_t)row * 4096 + kb);
                }
                #pragma unroll
                for (int p = 0; p < 16; p++) {
                    const int k = b_k0 + p * 4;
                    float4 v = *reinterpret_cast<const float4*>(Bp + (size_t)(kb + k) * 2048);
                    const uint32_t off = swzB((uint32_t)(k * 256 + b_n4 * 8));
                    *reinterpret_cast<uint2*>(stg + 16384 + off) =
                        make_uint2(pkh(v.x, v.y), pkh(v.z, v.w));
                }
                MBAR_ARRIVE(full0 + 8 * s);
                if (++s == 4) { s = 0; u ^= 1; }
            }
        }
        return;
    }

    const int wm = wid >> 1, wn = wid & 1;
    const int lane15 = lane & 15, seg = (lane >> 4) * 16;
    const uint32_t lxor = (uint32_t)((lane & 7) << 4);
    uint32_t a_row[2], b_colx[4];
    #pragma unroll
    for (int st = 0; st < 2; st++)
        a_row[st] = (uint32_t)((wm * 32 + st * 16 + lane15) * 128);
    #pragma unroll
    for (int ng = 0; ng < 4; ng++)
        b_colx[ng] = (uint32_t)(((wn * 64 + ng * 16) * 2 + seg)) ^ lxor;
    const uint32_t b_rowb = (uint32_t)(lane15 * 256);

    int s = 0, u = 0;
    for (int t = blockIdx.x; t < TOT; t += gridDim.x) {
        const int e = t >> 7, r = t & 127, sup = r >> 6, r2 = r & 63;
        const int mt = r2 & 7, nt = sup * 8 + (r2 >> 3);
        float acc[2][8][4];
        #pragma unroll
        for (int st = 0; st < 2; st++)
            #pragma unroll
            for (int j = 0; j < 8; j++)
                #pragma unroll
                for (int i = 0; i < 4; i++) acc[st][j][i] = 0.0f;

        for (int c = 0; c < NC; c++) {
            MBAR_WAIT(full0 + 8 * s, u);
            const uint32_t AhU = tiles_u + s * ST2;
            const uint32_t BhU = AhU + 16384;
            #pragma unroll
            for (int ks = 0; ks < 4; ks++) {
                const uint32_t acol = (uint32_t)(ks * 32 + seg) ^ lxor;
                const uint32_t brow = b_rowb + (uint32_t)(ks * 4096);
                uint32_t ah[2][4], bh[4][4];
                #pragma unroll
                for (int st = 0; st < 2; st++)
                    ldsm4(ah[st], AhU + a_row[st] + acol);
                #pragma unroll
                for (int ng = 0; ng < 4; ng++)
                    ldsm4t(bh[ng], BhU + brow + b_colx[ng]);
                #pragma unroll
                for (int st = 0; st < 2; st++)
                    #pragma unroll
                    for (int ng = 0; ng < 4; ng++)
                        #pragma unroll
                        for (int hf = 0; hf < 2; hf++)
                            mma16816(acc[st][ng * 2 + hf], ah[st], &bh[ng][2 * hf]);
            }
            if (lane == 0) MBAR_ARRIVE(empty0 + 8 * s);
            if (++s == 4) { s = 0; u ^= 1; }
        }
        float* Ce = C_ + (size_t)(e * 1024 + mt * 128) * 2048 + nt * 128;
        #pragma unroll
        for (int st = 0; st < 2; st++)
            #pragma unroll
            for (int j = 0; j < 8; j++) {
                const int r0 = wm * 32 + st * 16 + (lane >> 2);
                const int cc = wn * 64 + j * 8 + (lane & 3) * 2;
                float2 v0; v0.x = acc[st][j][0]; v0.y = acc[st][j][1];
                float2 v1; v1.x = acc[st][j][2]; v1.y = acc[st][j][3];
                *reinterpret_cast<float2*>(Ce + (size_t)r0 * 2048 + cc) = v0;
                *reinterpret_cast<float2*>(Ce + (size_t)(r0 + 8) * 2048 + cc) = v1;
            }
    }
}

// ============================================================================
extern "C" void kernel_launch(void* const* d_in, const int* in_sizes, int n_in,
                              void* d_out, int out_size) {
    const float* X   = (const float*)d_in[0];   // (8192, 2048)
    const float* Wgu = (const float*)d_in[1];   // (8, 2048, 8192)
    const float* Wd  = (const float*)d_in[2];   // (8, 4096, 2048)
    float* out = (float*)d_out;                 // (8192, 2048)

    cudaFuncSetAttribute(gemm1_ker, cudaFuncAttributeMaxDynamicSharedMemorySize, SMEM1);
    cudaFuncSetAttribute(gemm2_ker, cudaFuncAttributeMaxDynamicSharedMemorySize, SMEM2);

    gemm1_ker<<<NSM, 320, SMEM1>>>(X, Wgu);
    gemm2_ker<<<NSM, 384, SMEM2>>>(Wd, out);
}

// round 14
// speedup vs baseline: 1.9483x; 1.9483x over previous
#include <cuda_runtime.h>
#include <cuda_fp16.h>
#include <stdint.h>

// ============================================================================
// Llama4TextExperts grouped GEMM + SwiGLU, fp32 in/out.
// Single-term fp16 HMMA (mma.m16n8k16.f32.f16), fp32 accumulate.
// Persistent warp-specialized: 8 consumer warps @32x64 (4m x 2n) + 4 producer
// warps, 4-stage 32KB smem ring. Consumer k-steps are software-pipelined
// (double-buffered fragments: LDSM of ks+1 issues before MMAs of ks).
//   GEMM1: X(8,1024,2048) @ Wgu -> SwiGLU -> g_scr (fp16, 64MB)
//   GEMM2: g_scr @ Wd -> out (8192,2048) fp32
// ============================================================================

#define STAGE_BYTES 32768
#define NSTAGE 4
#define SMEM_BYTES (1024 + NSTAGE * STAGE_BYTES)
#define NSM 148

static __device__ __half g_scr[(size_t)8 * 1024 * 4096];   // 64 MB fp16 inter

// ---------------- helpers ----------------
__device__ __forceinline__ uint32_t s2u(const void* p) {
    uint32_t a;
    asm("{ .reg .u64 t; cvta.to.shared.u64 t, %1; cvt.u32.u64 %0, t; }" : "=r"(a) : "l"(p));
    return a;
}
__device__ __forceinline__ uint32_t swzA(uint32_t o) { return o ^ ((o >> 3) & 0x70); }  // 128B rows
__device__ __forceinline__ uint32_t swzB(uint32_t o) { return o ^ ((o >> 4) & 0x70); }  // 256B rows

__device__ __forceinline__ uint32_t pkh(float a, float b) {
    __half2 h = __floats2half2_rn(a, b);   // .x=a in low 16 bits
    return *reinterpret_cast<uint32_t*>(&h);
}
__device__ __forceinline__ float silu_mul(float g, float u) {
    return u * __fdividef(g, 1.0f + __expf(-g));
}

__device__ __forceinline__ void ldsm4(uint32_t* r, uint32_t addr) {
    asm volatile("ldmatrix.sync.aligned.m8n8.x4.shared.b16 {%0,%1,%2,%3}, [%4];"
                 : "=r"(r[0]), "=r"(r[1]), "=r"(r[2]), "=r"(r[3]) : "r"(addr));
}
__device__ __forceinline__ void ldsm4t(uint32_t* r, uint32_t addr) {
    asm volatile("ldmatrix.sync.aligned.m8n8.x4.trans.shared.b16 {%0,%1,%2,%3}, [%4];"
                 : "=r"(r[0]), "=r"(r[1]), "=r"(r[2]), "=r"(r[3]) : "r"(addr));
}
__device__ __forceinline__ void mma16816(float* c, const uint32_t* a, const uint32_t* b) {
    asm volatile(
        "mma.sync.aligned.m16n8k16.row.col.f32.f16.f16.f32 "
        "{%0,%1,%2,%3}, {%4,%5,%6,%7}, {%8,%9}, {%0,%1,%2,%3};"
        : "+f"(c[0]), "+f"(c[1]), "+f"(c[2]), "+f"(c[3])
        : "r"(a[0]), "r"(a[1]), "r"(a[2]), "r"(a[3]), "r"(b[0]), "r"(b[1]));
}

#define MBAR_INIT(addr, cnt) \
    asm volatile("mbarrier.init.shared.b64 [%0], %1;" :: "r"(addr), "r"((uint32_t)(cnt)) : "memory")
#define MBAR_ARRIVE(addr) \
    asm volatile("mbarrier.arrive.shared.b64 _, [%0];" :: "r"(addr) : "memory")
#define MBAR_WAIT(mbar_addr, phase_parity) do {                                            \
    uint32_t _mbar = (uint32_t)(mbar_addr);                                                \
    uint32_t _par  = (uint32_t)(phase_parity);                                             \
    uint32_t _done;                                                                        \
    asm volatile(                                                                          \
        "{\n\t.reg .pred p;\n\t"                                                           \
        "mbarrier.try_wait.parity.acquire.cta.shared::cta.b64 p, [%1], %2;\n\t"            \
        "selp.b32 %0, 1, 0, p;\n\t}"                                                       \
        : "=r"(_done) : "r"(_mbar), "r"(_par) : "memory");                                 \
    if (!_done) {                                                                          \
        asm volatile(                                                                      \
            "{\n\t.reg .pred P1;\n\t"                                                      \
            "WL_%=:\n\t"                                                                   \
            "mbarrier.try_wait.parity.acquire.cta.shared::cta.b64 P1, [%0], %1, 0x989680;\n\t" \
            "@P1 bra.uni WD_%=;\n\t"                                                       \
            "bra.uni WL_%=;\n\t"                                                           \
            "WD_%=:\n\t}"                                                                  \
            :: "r"(_mbar), "r"(_par) : "memory");                                          \
    }                                                                                      \
} while (0)

// ============================================================================
//   KDIM : reduction dim (2048 / 4096),  NTILE: n-tiles per expert (64 / 16)
//   MODE2=false: GEMM1. A = X fp32 (w2048) -> fp16. B = Wgu (w8192), warp-
//                paired gate/up at 32-col granularity: tile col n' ->
//                w=n'>>6, local=n'&63, kind=(local>>5)&1, pair=local&31;
//                global col = nt*64 + w*32 + pair + kind*4096.
//                Epilogue: register SwiGLU -> g_scr fp16.
//   MODE2=true : GEMM2. A = g_scr fp16 (w4096, raw copy); B = Wd; C fp32.
// Stage (32KB): Ah@0 (128 rows x 128B, swzA), Bh@16K (64 k-rows x 256B, swzB).
// Consumers: 8 warps, 4(m) x 2(n), 32x64 tiles, ks software pipeline.
// Producers: 4 warps.
// ============================================================================
template <int KDIM, int NTILE, bool MODE2>
__global__ __launch_bounds__(384, 1) void gemm_ker(const float* __restrict__ A_,
                                                   const float* __restrict__ B_,
                                                   float* __restrict__ C_) {
    extern __shared__ char smem[];
    constexpr int NC   = KDIM / 64;
    constexpr int NWB  = MODE2 ? 2048 : 8192;   // B row width
    constexpr int PERE = 8 * NTILE;             // tiles per expert
    constexpr int TOT  = 8 * PERE;              // total tiles

    const int tid  = threadIdx.x;
    const int wid  = tid >> 5;
    const int lane = tid & 31;

    const uint32_t smbase  = s2u(smem);
    const uint32_t tiles_u = (smbase + 1023) & ~1023u;
    char* tiles = smem + (tiles_u - smbase);
    const uint32_t full0  = smbase;        // full[s]  @ +8s, count=128
    const uint32_t empty0 = smbase + 32;   // empty[s] @ +8s, count=8

    if (tid == 0) {
        #pragma unroll
        for (int s = 0; s < NSTAGE; s++) {
            MBAR_INIT(full0 + 8 * s, 128);
            MBAR_INIT(empty0 + 8 * s, 8);
        }
    }
    __syncthreads();

    if (tid >= 256) {
        // ===================== PRODUCERS (warps 8..11) =====================
        const int pt   = tid - 256;          // 0..127
        const int a_c4 = pt & 15;            // 8B unit within 128B A row
        const int a_r0 = pt >> 4;            // 0..7
        const int b_n4 = pt & 31;            // 4-col unit in 128-n B row
        const int b_k0 = pt >> 5;            // 0..3

        int s = 0, u = 0;
        for (int t = blockIdx.x; t < TOT; t += gridDim.x) {
            const int e   = t / PERE;
            const int r   = t % PERE;
            const int sup = r >> 6;
            const int r2  = r & 63;
            const int mt  = r2 & 7;
            const int nt  = sup * 8 + (r2 >> 3);

            const float*  Apf = nullptr;
            const __half* Aph = nullptr;
            if (MODE2) Aph = g_scr + (size_t)(e * 1024 + mt * 128) * 4096 + a_c4 * 4;
            else       Apf = A_ + (size_t)(e * 1024 + mt * 128) * 2048 + a_c4 * 4;

            size_t bcol;
            if (MODE2) {
                bcol = (size_t)nt * 128 + b_n4 * 4;
            } else {
                const int np    = b_n4 * 4;
                const int w     = np >> 6;
                const int local = np & 63;
                const int kind  = (local >> 5) & 1;
                const int pair  = local & 31;
                bcol = (size_t)nt * 64 + w * 32 + pair + (size_t)kind * 4096;
            }
            const float* Bp = B_ + (size_t)e * KDIM * NWB + bcol;

            for (int c = 0; c < NC; c++) {
                MBAR_WAIT(empty0 + 8 * s, u ^ 1);
                char* stg = tiles + s * STAGE_BYTES;
                const int kb = c * 64;

                // ---- A tile: 128 rows x 64 k fp16 ----
                #pragma unroll
                for (int p = 0; p < 16; p++) {
                    const int row = a_r0 + p * 8;
                    const uint32_t off = swzA((uint32_t)(row * 128 + a_c4 * 8));
                    if (MODE2) {
                        *reinterpret_cast<uint2*>(stg + off) =
                            *reinterpret_cast<const uint2*>(Aph + (size_t)row * 4096 + kb);
                    } else {
                        float4 v = *reinterpret_cast<const float4*>(Apf + (size_t)row * 2048 + kb);
                        *reinterpret_cast<uint2*>(stg + off) =
                            make_uint2(pkh(v.x, v.y), pkh(v.z, v.w));
                    }
                }
                // ---- B tile: 64 k-rows x 128 n fp16 ----
                #pragma unroll
                for (int p = 0; p < 16; p++) {
                    const int k = b_k0 + p * 4;
                    float4 v = *reinterpret_cast<const float4*>(Bp + (size_t)(kb + k) * NWB);
                    const uint32_t off = swzB((uint32_t)(k * 256 + b_n4 * 8));
                    *reinterpret_cast<uint2*>(stg + 16384 + off) =
                        make_uint2(pkh(v.x, v.y), pkh(v.z, v.w));
                }
                MBAR_ARRIVE(full0 + 8 * s);
                if (++s == NSTAGE) { s = 0; u ^= 1; }
            }
        }
        return;
    }

    // ======================= CONSUMERS (warps 0..7) =======================
    // 4(m) x 2(n) warp grid, 32x64 tiles: wm = wid>>1 (0..3), wn = wid&1.
    const int wm = wid >> 1;
    const int wn = wid & 1;

    const int lane15 = lane & 15;
    const int seg    = (lane >> 4) * 16;
    const uint32_t lxor = (uint32_t)((lane & 7) << 4);
    uint32_t a_row[2], b_colx[4];
    #pragma unroll
    for (int st = 0; st < 2; st++)
        a_row[st] = (uint32_t)((wm * 32 + st * 16 + lane15) * 128);
    #pragma unroll
    for (int ng = 0; ng < 4; ng++)
        b_colx[ng] = (uint32_t)(((wn * 64 + ng * 16) * 2 + seg)) ^ lxor;
    const uint32_t b_rowb = (uint32_t)(lane15 * 256);

    int s = 0, u = 0;
    for (int t = blockIdx.x; t < TOT; t += gridDim.x) {
        const int e   = t / PERE;
        const int r   = t % PERE;
        const int sup = r >> 6;
        const int r2  = r & 63;
        const int mt  = r2 & 7;
        const int nt  = sup * 8 + (r2 >> 3);

        float acc[2][8][4];
        #pragma unroll
        for (int st = 0; st < 2; st++)
            #pragma unroll
            for (int j = 0; j < 8; j++)
                #pragma unroll
                for (int i = 0; i < 4; i++) acc[st][j][i] = 0.0f;

        for (int c = 0; c < NC; c++) {
            MBAR_WAIT(full0 + 8 * s, u);
            const uint32_t AhU = tiles_u + s * STAGE_BYTES;
            const uint32_t BhU = AhU + 16384;

            // ---- software-pipelined k-steps: double-buffered fragments ----
            uint32_t ah[2][2][4], bh[2][4][4];
            {   // prime ks = 0
                const uint32_t acol0 = (uint32_t)seg ^ lxor;
                #pragma unroll
                for (int st = 0; st < 2; st++)
                    ldsm4(ah[0][st], AhU + a_row[st] + acol0);
                #pragma unroll
                for (int ng = 0; ng < 4; ng++)
                    ldsm4t(bh[0][ng], BhU + b_rowb + b_colx[ng]);
            }
            #pragma unroll
            for (int ks = 0; ks < 4; ks++) {
                const int cur = ks & 1;
                const int nxt = cur ^ 1;
                if (ks < 3) {   // prefetch ks+1 before MMAs of ks
                    const uint32_t acol = (uint32_t)((ks + 1) * 32 + seg) ^ lxor;
                    const uint32_t brow = b_rowb + (uint32_t)((ks + 1) * 4096);
                    #pragma unroll
                    for (int st = 0; st < 2; st++)
                        ldsm4(ah[nxt][st], AhU + a_row[st] + acol);
                    #pragma unroll
                    for (int ng = 0; ng < 4; ng++)
                        ldsm4t(bh[nxt][ng], BhU + brow + b_colx[ng]);
                }
                #pragma unroll
                for (int st = 0; st < 2; st++)
                    #pragma unroll
                    for (int ng = 0; ng < 4; ng++)
                        #pragma unroll
                        for (int hf = 0; hf < 2; hf++)
                            mma16816(acc[st][ng * 2 + hf], ah[cur][st], &bh[cur][ng][2 * hf]);
            }
            if (lane == 0) MBAR_ARRIVE(empty0 + 8 * s);
            if (++s == NSTAGE) { s = 0; u ^= 1; }
        }

        // ----------------- epilogue (register-only, overlaps ring) --------
        if (MODE2) {
            float* Ce = C_ + (size_t)(e * 1024 + mt * 128) * 2048 + nt * 128;
            #pragma unroll
            for (int st = 0; st < 2; st++)
                #pragma unroll
                for (int j = 0; j < 8; j++) {
                    const int r0 = wm * 32 + st * 16 + (lane >> 2);
                    const int cc = wn * 64 + j * 8 + (lane & 3) * 2;
                    float2 v0; v0.x = acc[st][j][0]; v0.y = acc[st][j][1];
                    float2 v1; v1.x = acc[st][j][2]; v1.y = acc[st][j][3];
                    *reinterpret_cast<float2*>(Ce + (size_t)r0 * 2048 + cc) = v0;
                    *reinterpret_cast<float2*>(Ce + (size_t)(r0 + 8) * 2048 + cc) = v1;
                }
        } else {
            // gate = acc[st][j] (local cols 0..31), up = acc[st][j+4]
            // (local cols 32..63), same output pair. Register SwiGLU.
            __half* scrb = g_scr + (size_t)(e * 1024 + mt * 128) * 4096
                         + (size_t)nt * 64 + wn * 32;
            #pragma unroll
            for (int st = 0; st < 2; st++)
                #pragma unroll
                for (int j = 0; j < 4; j++) {
                    const int r0 = wm * 32 + st * 16 + (lane >> 2);
                    const int cc = j * 8 + (lane & 3) * 2;
                    const float i0 = silu_mul(acc[st][j][0], acc[st][j + 4][0]);
                    const float i1 = silu_mul(acc[st][j][1], acc[st][j + 4][1]);
                    const float i2 = silu_mul(acc[st][j][2], acc[st][j + 4][2]);
                    const float i3 = silu_mul(acc[st][j][3], acc[st][j + 4][3]);
                    *reinterpret_cast<uint32_t*>(scrb + (size_t)r0 * 4096 + cc) = pkh(i0, i1);
                    *reinterpret_cast<uint32_t*>(scrb + (size_t)(r0 + 8) * 4096 + cc) = pkh(i2, i3);
                }
        }
    }
}

// ============================================================================
extern "C" void kernel_launch(void* const* d_in, const int* in_sizes, int n_in,
                              void* d_out, int out_size) {
    const float* X   = (const float*)d_in[0];   // (8192, 2048)
    const float* Wgu = (const float*)d_in[1];   // (8, 2048, 8192)
    const float* Wd  = (const float*)d_in[2];   // (8, 4096, 2048)
    float* out = (float*)d_out;                 // (8192, 2048)

    cudaFuncSetAttribute(gemm_ker<2048, 64, false>,
                         cudaFuncAttributeMaxDynamicSharedMemorySize, SMEM_BYTES);
    cudaFuncSetAttribute(gemm_ker<4096, 16, true>,
                         cudaFuncAttributeMaxDynamicSharedMemorySize, SMEM_BYTES);

    gemm_ker<2048, 64, false><<<NSM, 384, SMEM_BYTES>>>(X, Wgu, nullptr);
    gemm_ker<4096, 16, true><<<NSM, 384, SMEM_BYTES>>>(nullptr, Wd, out);
}

// round 15
// speedup vs baseline: 2.6992x; 1.3854x over previous
#include <cuda_runtime.h>
#include <cuda_fp16.h>
#include <stdint.h>

// ============================================================================
// Llama4TextExperts grouped GEMM + SwiGLU, fp32 in/out.
// Single-term fp16 HMMA (mma.m16n8k16.f32.f16), fp32 accumulate.
// Persistent warp-specialized: 4 consumer warps @64x64 (2m x 2n) + 4 producer
// warps (256 threads -> 256-reg cap, acc128 fits), 4-stage 32KB smem ring.
//   GEMM1: X(8,1024,2048) @ Wgu -> SwiGLU -> g_scr (fp16, 64MB)
//   GEMM2: g_scr @ Wd -> out (8192,2048) fp32
// ============================================================================

#define STAGE_BYTES 32768
#define NSTAGE 4
#define SMEM_BYTES (1024 + NSTAGE * STAGE_BYTES)
#define NSM 148

static __device__ __half g_scr[(size_t)8 * 1024 * 4096];   // 64 MB fp16 inter

// ---------------- helpers ----------------
__device__ __forceinline__ uint32_t s2u(const void* p) {
    uint32_t a;
    asm("{ .reg .u64 t; cvta.to.shared.u64 t, %1; cvt.u32.u64 %0, t; }" : "=r"(a) : "l"(p));
    return a;
}
__device__ __forceinline__ uint32_t swzA(uint32_t o) { return o ^ ((o >> 3) & 0x70); }  // 128B rows
__device__ __forceinline__ uint32_t swzB(uint32_t o) { return o ^ ((o >> 4) & 0x70); }  // 256B rows

__device__ __forceinline__ uint32_t pkh(float a, float b) {
    __half2 h = __floats2half2_rn(a, b);   // .x=a in low 16 bits
    return *reinterpret_cast<uint32_t*>(&h);
}
__device__ __forceinline__ float silu_mul(float g, float u) {
    return u * __fdividef(g, 1.0f + __expf(-g));
}

__device__ __forceinline__ void ldsm4(uint32_t* r, uint32_t addr) {
    asm volatile("ldmatrix.sync.aligned.m8n8.x4.shared.b16 {%0,%1,%2,%3}, [%4];"
                 : "=r"(r[0]), "=r"(r[1]), "=r"(r[2]), "=r"(r[3]) : "r"(addr));
}
__device__ __forceinline__ void ldsm4t(uint32_t* r, uint32_t addr) {
    asm volatile("ldmatrix.sync.aligned.m8n8.x4.trans.shared.b16 {%0,%1,%2,%3}, [%4];"
                 : "=r"(r[0]), "=r"(r[1]), "=r"(r[2]), "=r"(r[3]) : "r"(addr));
}
__device__ __forceinline__ void mma16816(float* c, const uint32_t* a, const uint32_t* b) {
    asm volatile(
        "mma.sync.aligned.m16n8k16.row.col.f32.f16.f16.f32 "
        "{%0,%1,%2,%3}, {%4,%5,%6,%7}, {%8,%9}, {%0,%1,%2,%3};"
        : "+f"(c[0]), "+f"(c[1]), "+f"(c[2]), "+f"(c[3])
        : "r"(a[0]), "r"(a[1]), "r"(a[2]), "r"(a[3]), "r"(b[0]), "r"(b[1]));
}

#define MBAR_INIT(addr, cnt) \
    asm volatile("mbarrier.init.shared.b64 [%0], %1;" :: "r"(addr), "r"((uint32_t)(cnt)) : "memory")
#define MBAR_ARRIVE(addr) \
    asm volatile("mbarrier.arrive.shared.b64 _, [%0];" :: "r"(addr) : "memory")
#define MBAR_WAIT(mbar_addr, phase_parity) do {                                            \
    uint32_t _mbar = (uint32_t)(mbar_addr);                                                \
    uint32_t _par  = (uint32_t)(phase_parity);                                             \
    uint32_t _done;                                                                        \
    asm volatile(                                                                          \
        "{\n\t.reg .pred p;\n\t"                                                           \
        "mbarrier.try_wait.parity.acquire.cta.shared::cta.b64 p, [%1], %2;\n\t"            \
        "selp.b32 %0, 1, 0, p;\n\t}"                                                       \
        : "=r"(_done) : "r"(_mbar), "r"(_par) : "memory");                                 \
    if (!_done) {                                                                          \
        asm volatile(                                                                      \
            "{\n\t.reg .pred P1;\n\t"                                                      \
            "WL_%=:\n\t"                                                                   \
            "mbarrier.try_wait.parity.acquire.cta.shared::cta.b64 P1, [%0], %1, 0x989680;\n\t" \
            "@P1 bra.uni WD_%=;\n\t"                                                       \
            "bra.uni WL_%=;\n\t"                                                           \
            "WD_%=:\n\t}"                                                                  \
            :: "r"(_mbar), "r"(_par) : "memory");                                          \
    }                                                                                      \
} while (0)

// ============================================================================
//   KDIM : reduction dim (2048 / 4096),  NTILE: n-tiles per expert (64 / 16)
//   MODE2=false: GEMM1. A = X fp32 (w2048) -> fp16. B = Wgu (w8192), warp-
//                paired gate/up at 32-col granularity: tile col n' ->
//                w=n'>>6, local=n'&63, kind=(local>>5)&1, pair=local&31;
//                global col = nt*64 + w*32 + pair + kind*4096.
//                Epilogue: register SwiGLU -> g_scr fp16.
//   MODE2=true : GEMM2. A = g_scr fp16 (w4096, raw copy); B = Wd; C fp32.
// Stage (32KB): Ah@0 (128 rows x 128B, swzA), Bh@16K (64 k-rows x 256B, swzB).
// Consumers: 4 warps (wid 0..3), 2(m) x 2(n), 64x64 tiles.
// Producers: 4 warps (wid 4..7).
// ============================================================================
template <int KDIM, int NTILE, bool MODE2>
__global__ __launch_bounds__(256, 1) void gemm_ker(const float* __restrict__ A_,
                                                   const float* __restrict__ B_,
                                                   float* __restrict__ C_) {
    extern __shared__ char smem[];
    constexpr int NC   = KDIM / 64;
    constexpr int NWB  = MODE2 ? 2048 : 8192;   // B row width
    constexpr int PERE = 8 * NTILE;             // tiles per expert
    constexpr int TOT  = 8 * PERE;              // total tiles

    const int tid  = threadIdx.x;
    const int wid  = tid >> 5;
    const int lane = tid & 31;

    const uint32_t smbase  = s2u(smem);
    const uint32_t tiles_u = (smbase + 1023) & ~1023u;
    char* tiles = smem + (tiles_u - smbase);
    const uint32_t full0  = smbase;        // full[s]  @ +8s, count=128
    const uint32_t empty0 = smbase + 32;   // empty[s] @ +8s, count=4

    if (tid == 0) {
        #pragma unroll
        for (int s = 0; s < NSTAGE; s++) {
            MBAR_INIT(full0 + 8 * s, 128);
            MBAR_INIT(empty0 + 8 * s, 4);
        }
    }
    __syncthreads();

    if (tid >= 128) {
        // ===================== PRODUCERS (warps 4..7) =====================
        const int pt   = tid - 128;          // 0..127
        const int a_c4 = pt & 15;            // 8B unit within 128B A row
        const int a_r0 = pt >> 4;            // 0..7
        const int b_n4 = pt & 31;            // 4-col unit in 128-n B row
        const int b_k0 = pt >> 5;            // 0..3

        int s = 0, u = 0;
        for (int t = blockIdx.x; t < TOT; t += gridDim.x) {
            const int e   = t / PERE;
            const int r   = t % PERE;
            const int sup = r >> 6;
            const int r2  = r & 63;
            const int mt  = r2 & 7;
            const int nt  = sup * 8 + (r2 >> 3);

            const float*  Apf = nullptr;
            const __half* Aph = nullptr;
            if (MODE2) Aph = g_scr + (size_t)(e * 1024 + mt * 128) * 4096 + a_c4 * 4;
            else       Apf = A_ + (size_t)(e * 1024 + mt * 128) * 2048 + a_c4 * 4;

            size_t bcol;
            if (MODE2) {
                bcol = (size_t)nt * 128 + b_n4 * 4;
            } else {
                const int np    = b_n4 * 4;
                const int w     = np >> 6;
                const int local = np & 63;
                const int kind  = (local >> 5) & 1;
                const int pair  = local & 31;
                bcol = (size_t)nt * 64 + w * 32 + pair + (size_t)kind * 4096;
            }
            const float* Bp = B_ + (size_t)e * KDIM * NWB + bcol;

            for (int c = 0; c < NC; c++) {
                MBAR_WAIT(empty0 + 8 * s, u ^ 1);
                char* stg = tiles + s * STAGE_BYTES;
                const int kb = c * 64;

                // ---- A tile: 128 rows x 64 k fp16 ----
                #pragma unroll
                for (int p = 0; p < 16; p++) {
                    const int row = a_r0 + p * 8;
                    const uint32_t off = swzA((uint32_t)(row * 128 + a_c4 * 8));
                    if (MODE2) {
                        *reinterpret_cast<uint2*>(stg + off) =
                            *reinterpret_cast<const uint2*>(Aph + (size_t)row * 4096 + kb);
                    } else {
                        float4 v = *reinterpret_cast<const float4*>(Apf + (size_t)row * 2048 + kb);
                        *reinterpret_cast<uint2*>(stg + off) =
                            make_uint2(pkh(v.x, v.y), pkh(v.z, v.w));
                    }
                }
                // ---- B tile: 64 k-rows x 128 n fp16 ----
                #pragma unroll
                for (int p = 0; p < 16; p++) {
                    const int k = b_k0 + p * 4;
                    float4 v = *reinterpret_cast<const float4*>(Bp + (size_t)(kb + k) * NWB);
                    const uint32_t off = swzB((uint32_t)(k * 256 + b_n4 * 8));
                    *reinterpret_cast<uint2*>(stg + 16384 + off) =
                        make_uint2(pkh(v.x, v.y), pkh(v.z, v.w));
                }
                MBAR_ARRIVE(full0 + 8 * s);
                if (++s == NSTAGE) { s = 0; u ^= 1; }
            }
        }
        return;
    }

    // ======================= CONSUMERS (warps 0..3) =======================
    // 2(m) x 2(n) warp grid, 64x64 tiles: wm = wid>>1 (0..1), wn = wid&1.
    const int wm = wid >> 1;
    const int wn = wid & 1;

    const int lane15 = lane & 15;
    const int seg    = (lane >> 4) * 16;
    const uint32_t lxor = (uint32_t)((lane & 7) << 4);
    uint32_t a_row[4], b_colx[4];
    #pragma unroll
    for (int st = 0; st < 4; st++)
        a_row[st] = (uint32_t)((wm * 64 + st * 16 + lane15) * 128);
    #pragma unroll
    for (int ng = 0; ng < 4; ng++)
        b_colx[ng] = (uint32_t)(((wn * 64 + ng * 16) * 2 + seg)) ^ lxor;
    const uint32_t b_rowb = (uint32_t)(lane15 * 256);

    int s = 0, u = 0;
    for (int t = blockIdx.x; t < TOT; t += gridDim.x) {
        const int e   = t / PERE;
        const int r   = t % PERE;
        const int sup = r >> 6;
        const int r2  = r & 63;
        const int mt  = r2 & 7;
        const int nt  = sup * 8 + (r2 >> 3);

        float acc[4][8][4];
        #pragma unroll
        for (int st = 0; st < 4; st++)
            #pragma unroll
            for (int j = 0; j < 8; j++)
                #pragma unroll
                for (int i = 0; i < 4; i++) acc[st][j][i] = 0.0f;

        for (int c = 0; c < NC; c++) {
            MBAR_WAIT(full0 + 8 * s, u);
            const uint32_t AhU = tiles_u + s * STAGE_BYTES;
            const uint32_t BhU = AhU + 16384;

            #pragma unroll
            for (int ks = 0; ks < 4; ks++) {
                const uint32_t acol = (uint32_t)(ks * 32 + seg) ^ lxor;
                const uint32_t brow = b_rowb + (uint32_t)(ks * 4096);
                uint32_t ah[4][4], bh[4][4];
                #pragma unroll
                for (int st = 0; st < 4; st++)
                    ldsm4(ah[st], AhU + a_row[st] + acol);
                #pragma unroll
                for (int ng = 0; ng < 4; ng++)
                    ldsm4t(bh[ng], BhU + brow + b_colx[ng]);
                #pragma unroll
                for (int st = 0; st < 4; st++)
                    #pragma unroll
                    for (int ng = 0; ng < 4; ng++)
                        #pragma unroll
                        for (int hf = 0; hf < 2; hf++)
                            mma16816(acc[st][ng * 2 + hf], ah[st], &bh[ng][2 * hf]);
            }
            if (lane == 0) MBAR_ARRIVE(empty0 + 8 * s);
            if (++s == NSTAGE) { s = 0; u ^= 1; }
        }

        // ----------------- epilogue (register-only, overlaps ring) --------
        if (MODE2) {
            float* Ce = C_ + (size_t)(e * 1024 + mt * 128) * 2048 + nt * 128;
            #pragma unroll
            for (int st = 0; st < 4; st++)
                #pragma unroll
                for (int j = 0; j < 8; j++) {
                    const int r0 = wm * 64 + st * 16 + (lane >> 2);
                    const int cc = wn * 64 + j * 8 + (lane & 3) * 2;
                    float2 v0; v0.x = acc[st][j][0]; v0.y = acc[st][j][1];
                    float2 v1; v1.x = acc[st][j][2]; v1.y = acc[st][j][3];
                    *reinterpret_cast<float2*>(Ce + (size_t)r0 * 2048 + cc) = v0;
                    *reinterpret_cast<float2*>(Ce + (size_t)(r0 + 8) * 2048 + cc) = v1;
                }
        } else {
            // warp covers tile cols wn*64..wn*64+63: gate = acc[st][j]
            // (local 0..31), up = acc[st][j+4] (local 32..63), same out pair.
            __half* scrb = g_scr + (size_t)(e * 1024 + mt * 128) * 4096
                         + (size_t)nt * 64 + wn * 32;
            #pragma unroll
            for (int st = 0; st < 4; st++)
                #pragma unroll
                for (int j = 0; j < 4; j++) {
                    const int r0 = wm * 64 + st * 16 + (lane >> 2);
                    const int cc = j * 8 + (lane & 3) * 2;
                    const float i0 = silu_mul(acc[st][j][0], acc[st][j + 4][0]);
                    const float i1 = silu_mul(acc[st][j][1], acc[st][j + 4][1]);
                    const float i2 = silu_mul(acc[st][j][2], acc[st][j + 4][2]);
                    const float i3 = silu_mul(acc[st][j][3], acc[st][j + 4][3]);
                    *reinterpret_cast<uint32_t*>(scrb + (size_t)r0 * 4096 + cc) = pkh(i0, i1);
                    *reinterpret_cast<uint32_t*>(scrb + (size_t)(r0 + 8) * 4096 + cc) = pkh(i2, i3);
                }
        }
    }
}

// ============================================================================
extern "C" void kernel_launch(void* const* d_in, const int* in_sizes, int n_in,
                              void* d_out, int out_size) {
    const float* X   = (const float*)d_in[0];   // (8192, 2048)
    const float* Wgu = (const float*)d_in[1];   // (8, 2048, 8192)
    const float* Wd  = (const float*)d_in[2];   // (8, 4096, 2048)
    float* out = (float*)d_out;                 // (8192, 2048)

    cudaFuncSetAttribute(gemm_ker<2048, 64, false>,
                         cudaFuncAttributeMaxDynamicSharedMemorySize, SMEM_BYTES);
    cudaFuncSetAttribute(gemm_ker<4096, 16, true>,
                         cudaFuncAttributeMaxDynamicSharedMemorySize, SMEM_BYTES);

    gemm_ker<2048, 64, false><<<NSM, 256, SMEM_BYTES>>>(X, Wgu, nullptr);
    gemm_ker<4096, 16, true><<<NSM, 256, SMEM_BYTES>>>(nullptr, Wd, out);
}

// round 16
// speedup vs baseline: 2.9787x; 1.1035x over previous
#include <cuda_runtime.h>
#include <cuda_fp16.h>
#include <stdint.h>

// ============================================================================
// Llama4TextExperts grouped GEMM + SwiGLU, fp32 in/out.
// Single-term fp16 HMMA, cp.async multistage (no producer warps):
// 256 thr = 8 consumer warps (2m x 4n @64x64, CTA 128x256), 2 warps/SMSP.
//   prepass: X, Wgu, Wd fp32 -> fp16 globals
//   GEMM1: Xh @ Wguh -> SwiGLU -> g_scr (fp16)
//   GEMM2: g_scr @ Wdh -> out fp32
// ============================================================================

#define NSM 148
#define NST 4
#define STG_B 49152                       // A 16KB @0, B 32KB @16K
#define SMEM_BYTES (1024 + NST * STG_B)

static __device__ __half g_scr[(size_t)8 * 1024 * 4096];    // 64 MB
static __device__ __half Xh[(size_t)8192 * 2048];           // 32 MB
static __device__ __half Wguh[(size_t)8 * 2048 * 8192];     // 256 MB
static __device__ __half Wdh[(size_t)8 * 4096 * 2048];      // 128 MB

// ---------------- helpers ----------------
__device__ __forceinline__ uint32_t s2u(const void* p) {
    uint32_t a;
    asm("{ .reg .u64 t; cvta.to.shared.u64 t, %1; cvt.u32.u64 %0, t; }" : "=r"(a) : "l"(p));
    return a;
}
__device__ __forceinline__ uint32_t swzA(uint32_t o) { return o ^ ((o >> 3) & 0x70); }  // 128B rows
__device__ __forceinline__ uint32_t swzC(uint32_t o) { return o ^ ((o >> 5) & 0x70); }  // 512B rows

__device__ __forceinline__ uint32_t pkh(float a, float b) {
    __half2 h = __floats2half2_rn(a, b);
    return *reinterpret_cast<uint32_t*>(&h);
}
__device__ __forceinline__ float silu_mul(float g, float u) {
    return u * __fdividef(g, 1.0f + __expf(-g));
}
__device__ __forceinline__ void cpa16(uint32_t dst, const void* src) {
    asm volatile("cp.async.cg.shared.global [%0], [%1], 16;" :: "r"(dst), "l"(src) : "memory");
}
__device__ __forceinline__ void ldsm4(uint32_t* r, uint32_t addr) {
    asm volatile("ldmatrix.sync.aligned.m8n8.x4.shared.b16 {%0,%1,%2,%3}, [%4];"
                 : "=r"(r[0]), "=r"(r[1]), "=r"(r[2]), "=r"(r[3]) : "r"(addr));
}
__device__ __forceinline__ void ldsm4t(uint32_t* r, uint32_t addr) {
    asm volatile("ldmatrix.sync.aligned.m8n8.x4.trans.shared.b16 {%0,%1,%2,%3}, [%4];"
                 : "=r"(r[0]), "=r"(r[1]), "=r"(r[2]), "=r"(r[3]) : "r"(addr));
}
__device__ __forceinline__ void mma16816(float* c, const uint32_t* a, const uint32_t* b) {
    asm volatile(
        "mma.sync.aligned.m16n8k16.row.col.f32.f16.f16.f32 "
        "{%0,%1,%2,%3}, {%4,%5,%6,%7}, {%8,%9}, {%0,%1,%2,%3};"
        : "+f"(c[0]), "+f"(c[1]), "+f"(c[2]), "+f"(c[3])
        : "r"(a[0]), "r"(a[1]), "r"(a[2]), "r"(a[3]), "r"(b[0]), "r"(b[1]));
}

// ---------------- prepass: fp32 -> fp16 ----------------
__global__ __launch_bounds__(256) void cvt_ker(const float4* __restrict__ src,
                                               uint2* __restrict__ dst, int n4) {
    int i = blockIdx.x * 256 + threadIdx.x;
    const int stride = gridDim.x * 256;
    for (; i < n4; i += stride) {
        float4 v = src[i];
        dst[i] = make_uint2(pkh(v.x, v.y), pkh(v.z, v.w));
    }
}

// ============================================================================
//   KDIM : 2048 / 4096.  NTILE: 256-col n-tiles per expert (32 / 8).
//   MODE2=false: GEMM1. A = Xh (w2048). B = Wguh (w8192), gate/up paired at
//                32-col granularity per warp: tile col n' -> w=n'>>6,
//                kind=(n'>>5)&1, pair=n'&31; col = nt*128+w*32+pair+kind*4096.
//                Epilogue: register SwiGLU -> g_scr fp16.
//   MODE2=true : GEMM2. A = g_scr (w4096). B = Wdh (w2048). C fp32 (w2048).
// Stage (48KB): A@0 (128r x 128B, swzA), B@16K (64 k-rows x 512B, swzC).
// 8 warps, 2(m) x 4(n), 64x64 tiles; every warp issues cp.async too.
// ============================================================================
template <int KDIM, int NTILE, bool MODE2>
__global__ __launch_bounds__(256, 1) void gemm_ker(float* __restrict__ C_) {
    extern __shared__ char smem[];
    constexpr int NC   = KDIM / 64;
    constexpr int NWB  = MODE2 ? 2048 : 8192;   // B row width
    constexpr int AW   = MODE2 ? 4096 : 2048;   // A row width
    constexpr int PERE = 8 * NTILE;
    constexpr int TOT  = 8 * PERE;

    const int tid  = threadIdx.x;
    const int wid  = tid >> 5;
    const int lane = tid & 31;

    const uint32_t smbase  = s2u(smem);
    const uint32_t tiles_u = (smbase + 1023) & ~1023u;

    // ---- loader mapping (all threads) ----
    const int a_u  = tid & 7;            // 16B unit within 128B A row
    const int a_r0 = tid >> 3;           // 0..31 (stride 32, 4 iters)
    const int b_u  = tid & 31;           // 16B unit within 512B B row
    const int b_k0 = tid >> 5;           // 0..7 (stride 8, 8 iters)
    // gate/up pairing (GEMM1): nt-independent part of the B column
    int bloc;
    if (MODE2) bloc = b_u * 8;
    else {
        const int np = b_u * 8;
        bloc = (np >> 6) * 32 + (np & 31) + ((np >> 5) & 1) * 4096;
    }

    // ---- consumer fragment addressing ----
    const int wm = wid >> 2;             // 0..1  (64 m-rows each)
    const int wn = wid & 3;              // 0..3  (64 n-cols each)
    const int lane15 = lane & 15;
    const int seg    = (lane >> 4) * 16;
    const uint32_t lxor = (uint32_t)((lane & 7) << 4);
    uint32_t a_row[4], b_colx[4];
    #pragma unroll
    for (int st = 0; st < 4; st++)
        a_row[st] = (uint32_t)((wm * 64 + st * 16 + lane15) * 128);
    #pragma unroll
    for (int ng = 0; ng < 4; ng++)
        b_colx[ng] = (uint32_t)(((wn * 64 + ng * 16) * 2 + seg)) ^ lxor;
    const uint32_t b_rowb = (uint32_t)(lane15 * 512);

    for (int t = blockIdx.x; t < TOT; t += gridDim.x) {
        const int e   = t / PERE;
        const int r   = t % PERE;
        const int sup = r >> 6;
        const int r2  = r & 63;
        const int mt  = r2 & 7;
        const int nt  = MODE2 ? (r2 >> 3) : (sup * 8 + (r2 >> 3));

        const __half* Asrc = (MODE2 ? g_scr : Xh)
                           + (size_t)(e * 1024 + mt * 128) * AW;
        const __half* Bsrc = (MODE2 ? Wdh : Wguh)
                           + (size_t)e * KDIM * NWB
                           + (size_t)nt * (MODE2 ? 256 : 128) + bloc;

        // ---- cp.async issue for one chunk ----
        auto issue = [&](int c) {
            const uint32_t sb = tiles_u + (c & (NST - 1)) * STG_B;
            const int kb = c * 64;
            #pragma unroll
            for (int p = 0; p < 4; p++) {
                const int row = a_r0 + p * 32;
                cpa16(sb + swzA((uint32_t)(row * 128 + a_u * 16)),
                      Asrc + (size_t)row * AW + kb + a_u * 8);
            }
            #pragma unroll
            for (int p = 0; p < 8; p++) {
                const int k = b_k0 + p * 8;
                cpa16(sb + 16384 + swzC((uint32_t)(k * 512 + b_u * 16)),
                      Bsrc + (size_t)(kb + k) * NWB);
            }
            asm volatile("cp.async.commit_group;" ::: "memory");
        };

        // prologue: chunks 0..NST-2
        #pragma unroll
        for (int c0 = 0; c0 < NST - 1; c0++) issue(c0);

        float acc[4][8][4];
        #pragma unroll
        for (int st = 0; st < 4; st++)
            #pragma unroll
            for (int j = 0; j < 8; j++)
                #pragma unroll
                for (int i = 0; i < 4; i++) acc[st][j][i] = 0.0f;

        for (int c = 0; c < NC; c++) {
            if (c + 2 < NC) asm volatile("cp.async.wait_group 2;" ::: "memory");
            else            asm volatile("cp.async.wait_group 0;" ::: "memory");
            __syncthreads();

            const uint32_t AhU = tiles_u + (c & (NST - 1)) * STG_B;
            const uint32_t BhU = AhU + 16384;
            #pragma unroll
            for (int ks = 0; ks < 4; ks++) {
                const uint32_t acol = (uint32_t)(ks * 32 + seg) ^ lxor;
                const uint32_t brow = b_rowb + (uint32_t)(ks * 8192);
                uint32_t ah[4][4], bh[4][4];
                #pragma unroll
                for (int st = 0; st < 4; st++)
                    ldsm4(ah[st], AhU + a_row[st] + acol);
                #pragma unroll
                for (int ng = 0; ng < 4; ng++)
                    ldsm4t(bh[ng], BhU + brow + b_colx[ng]);
                #pragma unroll
                for (int st = 0; st < 4; st++)
                    #pragma unroll
                    for (int ng = 0; ng < 4; ng++)
                        #pragma unroll
                        for (int hf = 0; hf < 2; hf++)
                            mma16816(acc[st][ng * 2 + hf], ah[st], &bh[ng][2 * hf]);
            }
            if (c + NST - 1 < NC) issue(c + NST - 1);
        }

        // ----------------- epilogue (register-only) --------
        if (MODE2) {
            float* Ce = C_ + (size_t)(e * 1024 + mt * 128) * 2048
                      + (size_t)nt * 256 + wn * 64;
            #pragma unroll
            for (int st = 0; st < 4; st++)
                #pragma unroll
                for (int j = 0; j < 8; j++) {
                    const int r0 = wm * 64 + st * 16 + (lane >> 2);
                    const int cc = j * 8 + (lane & 3) * 2;
                    float2 v0; v0.x = acc[st][j][0]; v0.y = acc[st][j][1];
                    float2 v1; v1.x = acc[st][j][2]; v1.y = acc[st][j][3];
                    *reinterpret_cast<float2*>(Ce + (size_t)r0 * 2048 + cc) = v0;
                    *reinterpret_cast<float2*>(Ce + (size_t)(r0 + 8) * 2048 + cc) = v1;
                }
        } else {
            // warp tile cols wn*64..+63: gate = local 0..31 (j<4),
            // up = local 32..63 (j+4). Register SwiGLU -> g_scr.
            __half* scrb = g_scr + (size_t)(e * 1024 + mt * 128) * 4096
                         + (size_t)nt * 128 + wn * 32;
            #pragma unroll
            for (int st = 0; st < 4; st++)
                #pragma unroll
                for (int j = 0; j < 4; j++) {
                    const int r0 = wm * 64 + st * 16 + (lane >> 2);
                    const int cc = j * 8 + (lane & 3) * 2;
                    const float i0 = silu_mul(acc[st][j][0], acc[st][j + 4][0]);
                    const float i1 = silu_mul(acc[st][j][1], acc[st][j + 4][1]);
                    const float i2 = silu_mul(acc[st][j][2], acc[st][j + 4][2]);
                    const float i3 = silu_mul(acc[st][j][3], acc[st][j + 4][3]);
                    *reinterpret_cast<uint32_t*>(scrb + (size_t)r0 * 4096 + cc) = pkh(i0, i1);
                    *reinterpret_cast<uint32_t*>(scrb + (size_t)(r0 + 8) * 4096 + cc) = pkh(i2, i3);
                }
        }
        __syncthreads();   // protect stage slots before next tile's prologue
    }
}

// ============================================================================
extern "C" void kernel_launch(void* const* d_in, const int* in_sizes, int n_in,
                              void* d_out, int out_size) {
    const float* X   = (const float*)d_in[0];   // (8192, 2048)
    const float* Wgu = (const float*)d_in[1];   // (8, 2048, 8192)
    const float* Wd  = (const float*)d_in[2];   // (8, 4096, 2048)
    float* out = (float*)d_out;                 // (8192, 2048)

    __half *xh_p, *wguh_p, *wdh_p;
    cudaGetSymbolAddress((void**)&xh_p, Xh);
    cudaGetSymbolAddress((void**)&wguh_p, Wguh);
    cudaGetSymbolAddress((void**)&wdh_p, Wdh);

    cudaFuncSetAttribute(gemm_ker<2048, 32, false>,
                         cudaFuncAttributeMaxDynamicSharedMemorySize, SMEM_BYTES);
    cudaFuncSetAttribute(gemm_ker<4096, 8, true>,
                         cudaFuncAttributeMaxDynamicSharedMemorySize, SMEM_BYTES);

    // prepass conversions
    cvt_ker<<<2048, 256>>>((const float4*)X,   (uint2*)xh_p,   8192 * 2048 / 4);
    cvt_ker<<<4096, 256>>>((const float4*)Wgu, (uint2*)wguh_p, 8 * 2048 * 8192 / 4);
    cvt_ker<<<4096, 256>>>((const float4*)Wd,  (uint2*)wdh_p,  8 * 4096 * 2048 / 4);

    gemm_ker<2048, 32, false><<<NSM, 256, SMEM_BYTES>>>(nullptr);
    gemm_ker<4096, 8, true><<<NSM, 256, SMEM_BYTES>>>(out);
}